// round 16
// baseline (speedup 1.0000x reference)
#include <cuda_runtime.h>
#include <cuda_fp16.h>
#include <cstdint>
#include <cstddef>

// W8A16 GEMM, legacy-HMMA path (harness targets plain sm_103: tcgen05 unavailable).
// Contract (confirmed R4): X f32[M,K] (fp16-valued), W int32[N,K] (int8-valued),
// scale/bias f32[N], out f32[M,N] (fp16-rounded values).
// R16 = R7 mainloop (byte-identical; best: 1594us) made PERSISTENT:
// 2xSM CTAs grid-stride over tiles in linear (n-fastest) order; at each tile
// boundary the next tile's stage-0/1 cp.asyncs are issued BEFORE the epilogue
// so the prologue fill hides behind the output stores. Removes per-wave
// transitions and per-tile prologue stalls. Fused single converter kernel.

namespace {

constexpr int MM = 8192, KK = 4096, NN = 11008;
constexpr int BM = 128, BN = 128, BK = 64;
constexpr int THREADS = 256;
constexpr int STAGES = 3;
constexpr int KT = KK / BK;        // 64
constexpr int NT = NN / BN;        // 86 n-tiles
constexpr int TILES = (MM / BM) * NT;  // 5504
constexpr int ASTAGE = BM * 128;   // 16 KB
constexpr int BSTAGE = BN * 128;   // 16 KB
constexpr int SMEM_TOTAL = STAGES * (ASTAGE + BSTAGE);  // 96 KB
constexpr size_t GSTRIDE = (size_t)32 * KK;             // +32 rows, in elements

__device__ __align__(256) __half g_X16[(size_t)MM * KK];   // 64 MB
__device__ __align__(256) __half g_W16[(size_t)NN * KK];   // 90 MB

// ---------------- fused converter ----------------
constexpr int XCH = MM * KK / 8;
constexpr int WCH = NN * KK / 8;

__global__ void __launch_bounds__(256) cvt_xw(const float* __restrict__ x,
                                              const int* __restrict__ w) {
    int t = blockIdx.x * blockDim.x + threadIdx.x;
    if (t < XCH) {
        size_t base = (size_t)t * 8;
        const float4* p = (const float4*)(x + base);
        float4 a = p[0], b = p[1];
        __half2 h0 = __floats2half2_rn(a.x, a.y), h1 = __floats2half2_rn(a.z, a.w);
        __half2 h2 = __floats2half2_rn(b.x, b.y), h3 = __floats2half2_rn(b.z, b.w);
        uint4 o;
        o.x = *(uint32_t*)&h0; o.y = *(uint32_t*)&h1;
        o.z = *(uint32_t*)&h2; o.w = *(uint32_t*)&h3;
        *(uint4*)(g_X16 + base) = o;
    } else if (t < XCH + WCH) {
        size_t base = (size_t)(t - XCH) * 8;
        const int4* p = (const int4*)(w + base);
        int4 a = p[0], b = p[1];
        __half h[8];
        h[0] = __int2half_rn(a.x); h[1] = __int2half_rn(a.y);
        h[2] = __int2half_rn(a.z); h[3] = __int2half_rn(a.w);
        h[4] = __int2half_rn(b.x); h[5] = __int2half_rn(b.y);
        h[6] = __int2half_rn(b.z); h[7] = __int2half_rn(b.w);
        uint4 o;
        o.x = *(uint32_t*)&h[0]; o.y = *(uint32_t*)&h[2];
        o.z = *(uint32_t*)&h[4]; o.w = *(uint32_t*)&h[6];
        *(uint4*)(g_W16 + base) = o;
    }
}

// ---------------- helpers ----------------
__device__ __forceinline__ uint32_t swz(uint32_t x) { return x ^ ((x >> 3) & 0x70); }

__device__ __forceinline__ void cp_async16(uint32_t dst, const void* src) {
    asm volatile("cp.async.cg.shared.global [%0], [%1], 16;\n" :: "r"(dst), "l"(src));
}
__device__ __forceinline__ void cp_commit() { asm volatile("cp.async.commit_group;\n"); }
template <int N>
__device__ __forceinline__ void cp_wait() {
    asm volatile("cp.async.wait_group %0;\n" :: "n"(N) : "memory");
}

__device__ __forceinline__ void ldsm4(uint32_t r[4], uint32_t addr) {
    asm volatile("ldmatrix.sync.aligned.m8n8.x4.shared.b16 {%0,%1,%2,%3}, [%4];\n"
                 : "=r"(r[0]), "=r"(r[1]), "=r"(r[2]), "=r"(r[3]) : "r"(addr));
}

__device__ __forceinline__ void mma16816(float c[4], const uint32_t a[4],
                                         uint32_t b0, uint32_t b1) {
    asm volatile("mma.sync.aligned.m16n8k16.row.col.f32.f16.f16.f32 "
                 "{%0,%1,%2,%3}, {%4,%5,%6,%7}, {%8,%9}, {%0,%1,%2,%3};\n"
                 : "+f"(c[0]), "+f"(c[1]), "+f"(c[2]), "+f"(c[3])
                 : "r"(a[0]), "r"(a[1]), "r"(a[2]), "r"(a[3]), "r"(b0), "r"(b1));
}

__device__ __forceinline__ float rf16(float v) {
    return __half2float(__float2half_rn(v));
}

// ---------------- persistent GEMM ----------------
__global__ void __launch_bounds__(THREADS, 2)
gemm_kernel(const float* __restrict__ scale, const float* __restrict__ bias,
            float* __restrict__ out)
{
    extern __shared__ __align__(1024) char smem[];
    const uint32_t sA = (uint32_t)__cvta_generic_to_shared(smem);
    const uint32_t sB = sA + STAGES * ASTAGE;

    const int tid  = threadIdx.x;
    const int lane = tid & 31;
    const int warp = tid >> 5;
    const int wm = warp & 3;   // 4 warp rows x 32 M
    const int wn = warp >> 2;  // 2 warp cols x 64 N

    // constant staging geometry: 4 chunks/thread/operand, chunk i = +4096B smem
    const int row0 = tid >> 3, c0 = tid & 7;
    const uint32_t st0 = swz((uint32_t)(row0 * 128 + c0 * 16));

    // fragment offsets (constant)
    const uint32_t a_off0 = (uint32_t)((wm * 32 + (lane & 15)) * 128 + (lane >> 4) * 16);
    const uint32_t axor   = (a_off0 >> 3) & 0x70;
    const uint32_t b_off0 = (uint32_t)((wn * 64 + ((lane >> 4) & 1) * 8 + (lane & 7)) * 128
                                       + ((lane >> 3) & 1) * 16);
    const uint32_t bxor   = (b_off0 >> 3) & 0x70;

    int pid = blockIdx.x;
    if (pid >= TILES) return;

    // per-tile gmem bases (n-fastest order, matching the default raster)
    int m0 = (pid / NT) * BM;
    int n0 = (pid % NT) * BN;
    const __half* ag = g_X16 + (size_t)(m0 + row0) * KK + c0 * 8;
    const __half* bg = g_W16 + (size_t)(n0 + row0) * KK + c0 * 8;

    // prologue for first tile: stages 0 and 1
#pragma unroll
    for (int s = 0; s < 2; s++) {
        const size_t ko = (size_t)s * BK;
#pragma unroll
        for (int i = 0; i < 4; i++) cp_async16(sA + s * ASTAGE + st0 + i * 4096, ag + ko + i * GSTRIDE);
#pragma unroll
        for (int i = 0; i < 4; i++) cp_async16(sB + s * BSTAGE + st0 + i * 4096, bg + ko + i * GSTRIDE);
        cp_commit();
    }
    cp_wait<1>();
    __syncthreads();

    float acc[2][8][4];
#pragma unroll
    for (int mi = 0; mi < 2; mi++)
#pragma unroll
        for (int ni = 0; ni < 8; ni++)
#pragma unroll
            for (int e = 0; e < 4; e++) acc[mi][ni][e] = 0.f;

    while (true) {
        // ---- mainloop (identical to R7) ----
        for (int kt = 0; kt < KT; ++kt) {
            if (kt + 2 < KT) {
                const int s = (kt + 2) % STAGES;
                const size_t ko = (size_t)(kt + 2) * BK;
#pragma unroll
                for (int i = 0; i < 4; i++) cp_async16(sA + s * ASTAGE + st0 + i * 4096, ag + ko + i * GSTRIDE);
#pragma unroll
                for (int i = 0; i < 4; i++) cp_async16(sB + s * BSTAGE + st0 + i * 4096, bg + ko + i * GSTRIDE);
                cp_commit();
            }

            const uint32_t Abase = sA + (kt % STAGES) * ASTAGE;
            const uint32_t Bbase = sB + (kt % STAGES) * BSTAGE;
#pragma unroll
            for (int ks = 0; ks < 4; ++ks) {
                uint32_t a[2][4];
#pragma unroll
                for (int mi = 0; mi < 2; mi++)
                    ldsm4(a[mi], Abase + ((a_off0 + mi * 2048 + ks * 32) ^ axor));
#pragma unroll
                for (int np = 0; np < 4; np++) {
                    uint32_t b[4];
                    ldsm4(b, Bbase + ((b_off0 + np * 2048 + ks * 32) ^ bxor));
#pragma unroll
                    for (int mi = 0; mi < 2; mi++) {
                        mma16816(acc[mi][2 * np],     a[mi], b[0], b[1]);
                        mma16816(acc[mi][2 * np + 1], a[mi], b[2], b[3]);
                    }
                }
            }

            if (kt + 1 < KT) {
                if (kt + 2 < KT) cp_wait<1>(); else cp_wait<0>();
                __syncthreads();
            }
        }
        // pipe fully drained here (wait<0> at kt=KT-2); smem reads done after
        // this barrier:
        __syncthreads();

        const int cur_m0 = m0, cur_n0 = n0;
        pid += gridDim.x;
        const bool more = pid < TILES;
        if (more) {
            // next tile's prologue BEFORE the epilogue: fill hides behind stores
            m0 = (pid / NT) * BM;
            n0 = (pid % NT) * BN;
            ag = g_X16 + (size_t)(m0 + row0) * KK + c0 * 8;
            bg = g_W16 + (size_t)(n0 + row0) * KK + c0 * 8;
#pragma unroll
            for (int s = 0; s < 2; s++) {
                const size_t ko = (size_t)s * BK;
#pragma unroll
                for (int i = 0; i < 4; i++) cp_async16(sA + s * ASTAGE + st0 + i * 4096, ag + ko + i * GSTRIDE);
#pragma unroll
                for (int i = 0; i < 4; i++) cp_async16(sB + s * BSTAGE + st0 + i * 4096, bg + ko + i * GSTRIDE);
                cp_commit();
            }
        }

        // ---- epilogue (registers + gmem only) ----
        {
            const int gi = lane >> 2;
            const int tl = lane & 3;
#pragma unroll
            for (int ni = 0; ni < 8; ni++) {
                const int n = cur_n0 + wn * 64 + ni * 8 + tl * 2;
                const float s0 = __ldg(scale + n), s1 = __ldg(scale + n + 1);
                const float z0 = __ldg(bias + n),  z1 = __ldg(bias + n + 1);
#pragma unroll
                for (int mi = 0; mi < 2; mi++) {
                    const size_t r0 = (size_t)(cur_m0 + wm * 32 + mi * 16 + gi);
                    *(float2*)(out + r0 * NN + n) =
                        make_float2(rf16(acc[mi][ni][0] * s0 + z0), rf16(acc[mi][ni][1] * s1 + z1));
                    *(float2*)(out + (r0 + 8) * NN + n) =
                        make_float2(rf16(acc[mi][ni][2] * s0 + z0), rf16(acc[mi][ni][3] * s1 + z1));
                }
            }
        }

        if (!more) break;

        // re-zero accumulators for the next tile
#pragma unroll
        for (int mi = 0; mi < 2; mi++)
#pragma unroll
            for (int ni = 0; ni < 8; ni++)
#pragma unroll
                for (int e = 0; e < 4; e++) acc[mi][ni][e] = 0.f;

        cp_wait<1>();
        __syncthreads();
    }
}

struct ForceLoad {
    ForceLoad() {
        cudaFuncAttributes a;
        cudaFuncGetAttributes(&a, (const void*)cvt_xw);
        cudaFuncGetAttributes(&a, (const void*)gemm_kernel);
        cudaFuncSetAttribute((const void*)gemm_kernel,
                             cudaFuncAttributeMaxDynamicSharedMemorySize, SMEM_TOTAL);
    }
};
ForceLoad g_forceload;

} // namespace

extern "C" void kernel_launch(void* const* d_in, const int* in_sizes, int n_in,
                              void* d_out, int out_size) {
    const float* X     = (const float*)d_in[0];
    const int*   W     = (const int*)d_in[1];
    const float* scale = (const float*)d_in[2];
    const float* bias  = (const float*)d_in[3];
    float* out = (float*)d_out;

    const int total = XCH + WCH;
    cvt_xw<<<(total + 255) / 256, 256>>>(X, W);

    cudaFuncSetAttribute((const void*)gemm_kernel,
                         cudaFuncAttributeMaxDynamicSharedMemorySize, SMEM_TOTAL);

    int sms = 148;
    cudaDeviceGetAttribute(&sms, cudaDevAttrMultiProcessorCount, 0);
    int grid = 2 * sms;
    if (grid > TILES) grid = TILES;

    gemm_kernel<<<grid, THREADS, SMEM_TOTAL>>>(scale, bias, out);
}

// round 17
// speedup vs baseline: 1.0562x; 1.0562x over previous
#include <cuda_runtime.h>
#include <cuda_fp16.h>
#include <cstdint>
#include <cstddef>

// W8A16 GEMM, legacy-HMMA path (harness targets plain sm_103: tcgen05 unavailable).
// Contract (confirmed R4): X f32[M,K] (fp16-valued), W int32[N,K] (int8-valued),
// scale/bias f32[N], out f32[M,N] (fp16-rounded values).
// FINAL (= R15, best: 1594.0/1594.3us): fused single converter launch
// (X f32->fp16 scratch, W int32->fp16 scratch), then GEMM:
// 128x128 CTA tile, BK=64, 8 warps (32x64 warp tiles), 3-stage cp.async ring
// (wait_group 1), SW128 smem, ldmatrix + mma.sync.m16n8k16, 2 CTAs/SM,
// default x-major raster (86 consecutive CTAs share one L2-hot A slab).
// Ten perturbations (warp shapes, occupancy, registers, int8-B, fragment
// buffering, two rasterizations, persistence) all regressed or were neutral:
// this configuration is the measured optimum for the legacy-HMMA pipe here
// (tensor=79.4%, smem-crossbar/tensor co-bound).

namespace {

constexpr int MM = 8192, KK = 4096, NN = 11008;
constexpr int BM = 128, BN = 128, BK = 64;
constexpr int THREADS = 256;
constexpr int STAGES = 3;
constexpr int ASTAGE = BM * 128;   // 16 KB
constexpr int BSTAGE = BN * 128;   // 16 KB
constexpr int SMEM_TOTAL = STAGES * (ASTAGE + BSTAGE);  // 96 KB

__device__ __align__(256) __half g_X16[(size_t)MM * KK];   // 64 MB
__device__ __align__(256) __half g_W16[(size_t)NN * KK];   // 90 MB

// ---------------- fused converter ----------------
// Chunk t < XCH: 8 f32 -> 8 fp16 of X. Chunk t >= XCH: 8 int32 -> 8 fp16 of W.
constexpr int XCH = MM * KK / 8;
constexpr int WCH = NN * KK / 8;

__global__ void __launch_bounds__(256) cvt_xw(const float* __restrict__ x,
                                              const int* __restrict__ w) {
    int t = blockIdx.x * blockDim.x + threadIdx.x;
    if (t < XCH) {
        size_t base = (size_t)t * 8;
        const float4* p = (const float4*)(x + base);
        float4 a = p[0], b = p[1];
        __half2 h0 = __floats2half2_rn(a.x, a.y), h1 = __floats2half2_rn(a.z, a.w);
        __half2 h2 = __floats2half2_rn(b.x, b.y), h3 = __floats2half2_rn(b.z, b.w);
        uint4 o;
        o.x = *(uint32_t*)&h0; o.y = *(uint32_t*)&h1;
        o.z = *(uint32_t*)&h2; o.w = *(uint32_t*)&h3;
        *(uint4*)(g_X16 + base) = o;
    } else if (t < XCH + WCH) {
        size_t base = (size_t)(t - XCH) * 8;
        const int4* p = (const int4*)(w + base);
        int4 a = p[0], b = p[1];
        __half h[8];
        h[0] = __int2half_rn(a.x); h[1] = __int2half_rn(a.y);
        h[2] = __int2half_rn(a.z); h[3] = __int2half_rn(a.w);
        h[4] = __int2half_rn(b.x); h[5] = __int2half_rn(b.y);
        h[6] = __int2half_rn(b.z); h[7] = __int2half_rn(b.w);
        uint4 o;
        o.x = *(uint32_t*)&h[0]; o.y = *(uint32_t*)&h[2];
        o.z = *(uint32_t*)&h[4]; o.w = *(uint32_t*)&h[6];
        *(uint4*)(g_W16 + base) = o;
    }
}

// ---------------- helpers ----------------
__device__ __forceinline__ uint32_t swz(uint32_t x) { return x ^ ((x >> 3) & 0x70); }

__device__ __forceinline__ void cp_async16(uint32_t dst, const void* src) {
    asm volatile("cp.async.cg.shared.global [%0], [%1], 16;\n" :: "r"(dst), "l"(src));
}
__device__ __forceinline__ void cp_commit() { asm volatile("cp.async.commit_group;\n"); }
template <int N>
__device__ __forceinline__ void cp_wait() {
    asm volatile("cp.async.wait_group %0;\n" :: "n"(N) : "memory");
}

__device__ __forceinline__ void ldsm4(uint32_t r[4], uint32_t addr) {
    asm volatile("ldmatrix.sync.aligned.m8n8.x4.shared.b16 {%0,%1,%2,%3}, [%4];\n"
                 : "=r"(r[0]), "=r"(r[1]), "=r"(r[2]), "=r"(r[3]) : "r"(addr));
}

__device__ __forceinline__ void mma16816(float c[4], const uint32_t a[4],
                                         uint32_t b0, uint32_t b1) {
    asm volatile("mma.sync.aligned.m16n8k16.row.col.f32.f16.f16.f32 "
                 "{%0,%1,%2,%3}, {%4,%5,%6,%7}, {%8,%9}, {%0,%1,%2,%3};\n"
                 : "+f"(c[0]), "+f"(c[1]), "+f"(c[2]), "+f"(c[3])
                 : "r"(a[0]), "r"(a[1]), "r"(a[2]), "r"(a[3]), "r"(b0), "r"(b1));
}

__device__ __forceinline__ float rf16(float v) {
    return __half2float(__float2half_rn(v));
}

// ---------------- GEMM ----------------
__global__ void __launch_bounds__(THREADS, 2)
gemm_kernel(const float* __restrict__ scale, const float* __restrict__ bias,
            float* __restrict__ out, int M, int N, int K)
{
    extern __shared__ __align__(1024) char smem[];
    const uint32_t sA = (uint32_t)__cvta_generic_to_shared(smem);
    const uint32_t sB = sA + STAGES * ASTAGE;

    const int tid  = threadIdx.x;
    const int lane = tid & 31;
    const int warp = tid >> 5;
    const int wm = warp & 3;   // 4 warp rows x 32 M
    const int wn = warp >> 2;  // 2 warp cols x 64 N

    const int m0 = blockIdx.y * BM;
    const int n0 = blockIdx.x * BN;   // x = N: a wave shares the A slab, streams W
    const int KT = K / BK;

    // staging: 1024 x 16B chunks per operand stage, 4 per thread
    uint32_t a_st[4]; const __half* a_g[4]; const __half* b_g[4];
#pragma unroll
    for (int i = 0; i < 4; i++) {
        int chunk = tid + i * THREADS;
        int row = chunk >> 3, c = chunk & 7;
        a_st[i] = swz((uint32_t)(row * 128 + c * 16));
        a_g[i]  = g_X16 + (size_t)(m0 + row) * K + c * 8;
        b_g[i]  = g_W16 + (size_t)(n0 + row) * K + c * 8;
    }

    // ldmatrix base offsets (swizzle xor is row-only -> constant per thread)
    const uint32_t a_off0 = (uint32_t)((wm * 32 + (lane & 15)) * 128 + (lane >> 4) * 16);
    const uint32_t axor   = (a_off0 >> 3) & 0x70;
    const uint32_t b_off0 = (uint32_t)((wn * 64 + ((lane >> 4) & 1) * 8 + (lane & 7)) * 128
                                       + ((lane >> 3) & 1) * 16);
    const uint32_t bxor   = (b_off0 >> 3) & 0x70;

    float acc[2][8][4];
#pragma unroll
    for (int mi = 0; mi < 2; mi++)
#pragma unroll
        for (int ni = 0; ni < 8; ni++)
#pragma unroll
            for (int e = 0; e < 4; e++) acc[mi][ni][e] = 0.f;

    // prologue: stages 0 and 1
#pragma unroll
    for (int s = 0; s < 2; s++) {
        const size_t ko = (size_t)s * BK;
#pragma unroll
        for (int i = 0; i < 4; i++) cp_async16(sA + s * ASTAGE + a_st[i], a_g[i] + ko);
#pragma unroll
        for (int i = 0; i < 4; i++) cp_async16(sB + s * BSTAGE + a_st[i], b_g[i] + ko);
        cp_commit();
    }
    cp_wait<1>();          // stage 0 resident
    __syncthreads();

    for (int kt = 0; kt < KT; ++kt) {
        // issue loads for kt+2 into the buffer freed at the end of kt-1
        if (kt + 2 < KT) {
            const int s = (kt + 2) % STAGES;
            const size_t ko = (size_t)(kt + 2) * BK;
#pragma unroll
            for (int i = 0; i < 4; i++) cp_async16(sA + s * ASTAGE + a_st[i], a_g[i] + ko);
#pragma unroll
            for (int i = 0; i < 4; i++) cp_async16(sB + s * BSTAGE + a_st[i], b_g[i] + ko);
            cp_commit();
        }

        // compute stage kt
        const uint32_t Abase = sA + (kt % STAGES) * ASTAGE;
        const uint32_t Bbase = sB + (kt % STAGES) * BSTAGE;
#pragma unroll
        for (int ks = 0; ks < 4; ++ks) {
            uint32_t a[2][4];
#pragma unroll
            for (int mi = 0; mi < 2; mi++)
                ldsm4(a[mi], Abase + ((a_off0 + mi * 2048 + ks * 32) ^ axor));
#pragma unroll
            for (int np = 0; np < 4; np++) {
                uint32_t b[4];
                ldsm4(b, Bbase + ((b_off0 + np * 2048 + ks * 32) ^ bxor));
#pragma unroll
                for (int mi = 0; mi < 2; mi++) {
                    mma16816(acc[mi][2 * np],     a[mi], b[0], b[1]);
                    mma16816(acc[mi][2 * np + 1], a[mi], b[2], b[3]);
                }
            }
        }

        // ensure stage kt+1 resident before next iteration
        if (kt + 1 < KT) {
            if (kt + 2 < KT) cp_wait<1>(); else cp_wait<0>();
            __syncthreads();
        }
    }

    // epilogue: scale + bias, round through fp16, f32 out
    const int gi = lane >> 2;
    const int tl = lane & 3;
#pragma unroll
    for (int ni = 0; ni < 8; ni++) {
        const int n = n0 + wn * 64 + ni * 8 + tl * 2;
        const float s0 = __ldg(scale + n), s1 = __ldg(scale + n + 1);
        const float z0 = __ldg(bias + n),  z1 = __ldg(bias + n + 1);
#pragma unroll
        for (int mi = 0; mi < 2; mi++) {
            const size_t r0 = (size_t)(m0 + wm * 32 + mi * 16 + gi);
            *(float2*)(out + r0 * N + n) =
                make_float2(rf16(acc[mi][ni][0] * s0 + z0), rf16(acc[mi][ni][1] * s1 + z1));
            *(float2*)(out + (r0 + 8) * N + n) =
                make_float2(rf16(acc[mi][ni][2] * s0 + z0), rf16(acc[mi][ni][3] * s1 + z1));
        }
    }
}

struct ForceLoad {
    ForceLoad() {
        cudaFuncAttributes a;
        cudaFuncGetAttributes(&a, (const void*)cvt_xw);
        cudaFuncGetAttributes(&a, (const void*)gemm_kernel);
        cudaFuncSetAttribute((const void*)gemm_kernel,
                             cudaFuncAttributeMaxDynamicSharedMemorySize, SMEM_TOTAL);
    }
};
ForceLoad g_forceload;

} // namespace

extern "C" void kernel_launch(void* const* d_in, const int* in_sizes, int n_in,
                              void* d_out, int out_size) {
    const float* X     = (const float*)d_in[0];
    const int*   W     = (const int*)d_in[1];
    const float* scale = (const float*)d_in[2];
    const float* bias  = (const float*)d_in[3];
    float* out = (float*)d_out;

    const int n0 = in_sizes[0];
    const int n1 = in_sizes[1];
    const int N  = in_sizes[2];            // 11008
    const int K  = n1 / N;                 // 4096
    const int M  = n0 / K;                 // 8192

    const int total = XCH + WCH;
    cvt_xw<<<(total + 255) / 256, 256>>>(X, W);

    cudaFuncSetAttribute((const void*)gemm_kernel,
                         cudaFuncAttributeMaxDynamicSharedMemorySize, SMEM_TOTAL);
    dim3 grid(N / BN, M / BM);             // 86 x 64
    gemm_kernel<<<grid, THREADS, SMEM_TOTAL>>>(scale, bias, out, M, N, K);
}